// round 10
// baseline (speedup 1.0000x reference)
#include <cuda_runtime.h>
#include <math.h>

#define BB 4
#define TT 16
#define HH 64
#define WW 64
#define CIN 32
#define COUT 64
#define GG (4*COUT)   // 256 gate channels

typedef unsigned long long u64;

// Scratch: gx for all (b,t) pixels: (B*T*H*W, 256) floats = 268MB
__device__ float g_gx[(size_t)BB*TT*HH*WW*GG];
// Duplicated ping-pong hidden state: each channel stored as {h,h} pair
__device__ float g_h0d[(size_t)BB*HH*WW*COUT*2];
__device__ float g_h1d[(size_t)BB*HH*WW*COUT*2];
// Duplicated input x: per pixel {x0,x0,x1,x1,...} (16.8MB)
__device__ float g_xd[(size_t)BB*TT*HH*WW*CIN*2];
// Cell state
__device__ float g_c [(size_t)BB*HH*WW*COUT];
// Split transposed weights: [k][ci][lane(32)][4 floats]
// g01: {g0c0,g0c1,g1c0,g1c1}   g23: {g2c0,g2c1,g3c0,g3c1}   (c0=2*lane)
__device__ float g_rw01[9*COUT*32*4];
__device__ float g_rw23[9*COUT*32*4];
__device__ float g_wk01[9*CIN*32*4];
__device__ float g_wk23[9*CIN*32*4];

__device__ __forceinline__ float hsig(float z) {
    return fminf(fmaxf(0.2f*z + 0.5f, 0.0f), 1.0f);
}

__device__ __forceinline__ void fma_x2(u64& acc, u64 s, u64 w) {
    asm("fma.rn.f32x2 %0, %1, %2, %3;" : "=l"(acc) : "l"(s), "l"(w), "l"(acc));
}
__device__ __forceinline__ float2 unpack2(u64 v) {
    float2 f;
    asm("mov.b64 {%0, %1}, %2;" : "=f"(f.x), "=f"(f.y) : "l"(v));
    return f;
}

// ---------------------------------------------------------------------------
// Weight transpose prep.
// ---------------------------------------------------------------------------
__global__ __launch_bounds__(128)
void prep_weights(const float* __restrict__ wk, const float* __restrict__ rw)
{
    const int i = blockIdx.x * 128 + threadIdx.x;
    if (i < 9*COUT*32) {
        const int j  = i & 31;
        const int ci = (i >> 5) & 63;
        const int k  = i >> 11;
        const float* s = rw + ((size_t)(k*COUT + ci))*GG + 2*j;
        ((float4*)g_rw01)[i] = make_float4(s[0],   s[1],   s[64],  s[65]);
        ((float4*)g_rw23)[i] = make_float4(s[128], s[129], s[192], s[193]);
    }
    const int m = i - 9*COUT*32;
    if (m >= 0 && m < 9*CIN*32) {
        const int j  = m & 31;
        const int ci = (m >> 5) & 31;
        const int k  = m >> 10;
        const float* s = wk + ((size_t)(k*CIN + ci))*GG + 2*j;
        ((float4*)g_wk01)[m] = make_float4(s[0],   s[1],   s[64],  s[65]);
        ((float4*)g_wk23)[m] = make_float4(s[128], s[129], s[192], s[193]);
    }
}

// ---------------------------------------------------------------------------
// x pair-duplication prep: xd[px][2ci] = {x0,x0,x1,x1,...}
// One thread per (pixel, ci-pair). 4.2M threads.
// ---------------------------------------------------------------------------
__global__ __launch_bounds__(256)
void prep_xdup(const float* __restrict__ x)
{
    const size_t i = (size_t)blockIdx.x * 256 + threadIdx.x;   // px*16 + q
    const size_t px = i >> 4;
    const int q = (int)(i & 15);
    const float2 v = *(const float2*)(x + px*CIN + 2*q);
    ((float4*)g_xd)[px*16 + q] = make_float4(v.x, v.x, v.y, v.y);
}

// Chunked smem weight tile: [9 taps][4 ci][32 lanes] float4, for each of 2 arrays.
#define CHUNK 4
#define TILE4 (9*CHUNK*32)    // 1152 float4 per array

// ---------------------------------------------------------------------------
// Phase 1: input-to-gate conv with smem-staged weights and paired-x loads.
// Thread: 8 pixels x (2 channels x 4 gates) = 32 packed accumulators.
// Block: 128 thr = 4 warps x 32 lanes = 32 px. Grid: B*T*H*2 = 8192.
// ---------------------------------------------------------------------------
__global__ __launch_bounds__(128, 4)
void input_conv_kernel(const float* __restrict__ bias)
{
    __shared__ float4 s01[TILE4];
    __shared__ float4 s23[TILE4];

    const int tx   = threadIdx.x;
    const int lane = tx & 31;
    const int co0  = lane * 2;
    const int pg   = tx >> 5;
    const int bid  = blockIdx.x;
    const int bt   = bid >> 7;
    const int r    = bid & 127;
    const int py   = r >> 1;
    const int px0  = (r & 1) * 32 + pg * 8;
    const bool okL = (px0 > 0);
    const bool okR = (px0 < WW - 8);

    u64 acc[4][8];
    #pragma unroll
    for (int g = 0; g < 4; g++) {
        u64 bv = *(const u64*)(bias + g*COUT + co0);
        #pragma unroll
        for (int p = 0; p < 8; p++) acc[g][p] = bv;
    }

    const int iy0 = py - 1;
    const float* __restrict__ xbase = g_xd + ((size_t)(bt*HH))*WW*(CIN*2);

    #pragma unroll 1
    for (int cc = 0; cc < CIN; cc += CHUNK) {
        __syncthreads();
        #pragma unroll
        for (int i = tx; i < TILE4; i += 128) {
            const int tap  = i >> 7;          // /128
            const int rest = i & 127;
            const size_t src = (size_t)(tap*CIN + cc)*32 + rest;
            s01[i] = ((const float4*)g_wk01)[src];
            s23[i] = ((const float4*)g_wk23)[src];
        }
        __syncthreads();

        #pragma unroll
        for (int ky = 0; ky < 3; ky++) {
            const int iy = iy0 + ky;
            if ((unsigned)iy >= HH) continue;
            const float* __restrict__ xrow = xbase + ((size_t)iy*WW)*(CIN*2);
            #pragma unroll
            for (int qq = 0; qq < CHUNK/2; qq++) {
                const int fq = (cc >> 1) + qq;      // float4 slot within pixel
                ulonglong2 hv[10];
                hv[0] = okL ? *(const ulonglong2*)(xrow + (size_t)(px0-1)*(CIN*2) + fq*4)
                            : make_ulonglong2(0ULL, 0ULL);
                #pragma unroll
                for (int j = 1; j < 9; j++)
                    hv[j] = *(const ulonglong2*)(xrow + (size_t)(px0-1+j)*(CIN*2) + fq*4);
                hv[9] = okR ? *(const ulonglong2*)(xrow + (size_t)(px0+8)*(CIN*2) + fq*4)
                            : make_ulonglong2(0ULL, 0ULL);
                #pragma unroll
                for (int kx = 0; kx < 3; kx++) {
                    const int s0 = ((ky*3+kx)*CHUNK + 2*qq)*32 + lane;
                    const ulonglong2 wA0 = *reinterpret_cast<const ulonglong2*>(&s01[s0]);
                    const ulonglong2 wB0 = *reinterpret_cast<const ulonglong2*>(&s23[s0]);
                    const ulonglong2 wA1 = *reinterpret_cast<const ulonglong2*>(&s01[s0+32]);
                    const ulonglong2 wB1 = *reinterpret_cast<const ulonglong2*>(&s23[s0+32]);
                    #pragma unroll
                    for (int p = 0; p < 8; p++) {
                        const u64 se = hv[p + kx].x;   // even ci
                        const u64 so = hv[p + kx].y;   // odd ci
                        fma_x2(acc[0][p], se, wA0.x);
                        fma_x2(acc[1][p], se, wA0.y);
                        fma_x2(acc[2][p], se, wB0.x);
                        fma_x2(acc[3][p], se, wB0.y);
                        fma_x2(acc[0][p], so, wA1.x);
                        fma_x2(acc[1][p], so, wA1.y);
                        fma_x2(acc[2][p], so, wB1.x);
                        fma_x2(acc[3][p], so, wB1.y);
                    }
                }
            }
        }
    }

    const size_t rowbase = ((size_t)bt*HH + py)*WW;
    #pragma unroll
    for (int p = 0; p < 8; p++) {
        float* __restrict__ o = g_gx + (rowbase + px0 + p)*GG + co0;
        *(u64*)(o + 0*COUT) = acc[0][p];
        *(u64*)(o + 1*COUT) = acc[1][p];
        *(u64*)(o + 2*COUT) = acc[2][p];
        *(u64*)(o + 3*COUT) = acc[3][p];
    }
}

// ---------------------------------------------------------------------------
// Phase 2: one recurrent step with smem-staged weights and paired-h loads.
// Thread: 8 pixels x (2 channels x 4 gates) = 32 packed accumulators.
// Block: 128 thr = 4 warps x 32 lanes = 32 px. Grid: B*H*2 = 512.
// ---------------------------------------------------------------------------
template<bool FIRST>
__global__ __launch_bounds__(128, 4)
void step_kernel(float* __restrict__ y,
                 const int t,
                 const float* __restrict__ gamma,
                 const float* __restrict__ beta,
                 const float* __restrict__ mmean,
                 const float* __restrict__ mvar)
{
    __shared__ float4 s01[TILE4];
    __shared__ float4 s23[TILE4];

    const float* __restrict__ hprevd = (t & 1) ? g_h0d : g_h1d;
    float*       __restrict__ hnewd  = (t & 1) ? g_h1d : g_h0d;

    const int tx   = threadIdx.x;
    const int lane = tx & 31;
    const int co0  = lane * 2;
    const int pg   = tx >> 5;
    const int bid  = blockIdx.x;
    const int b    = bid >> 7;
    const int r    = bid & 127;
    const int py   = r >> 1;
    const int px0  = (r & 1) * 32 + pg * 8;
    const bool okL = (px0 > 0);
    const bool okR = (px0 < WW - 8);

    u64 acc[4][8];
    const size_t gxrow = ((size_t)(b*TT + t)*HH + py)*WW;
    #pragma unroll
    for (int p = 0; p < 8; p++) {
        const float* __restrict__ gp = g_gx + (gxrow + px0 + p)*GG + co0;
        acc[0][p] = *(const u64*)(gp + 0*COUT);
        acc[1][p] = *(const u64*)(gp + 1*COUT);
        acc[2][p] = *(const u64*)(gp + 2*COUT);
        acc[3][p] = *(const u64*)(gp + 3*COUT);
    }

    if (!FIRST) {
        const int iy0 = py - 1;
        const float* __restrict__ hbase = hprevd + ((size_t)(b*HH))*WW*(COUT*2);

        #pragma unroll 1
        for (int cc = 0; cc < COUT; cc += CHUNK) {
            __syncthreads();
            #pragma unroll
            for (int i = tx; i < TILE4; i += 128) {
                const int tap  = i >> 7;
                const int rest = i & 127;
                const size_t src = (size_t)(tap*COUT + cc)*32 + rest;
                s01[i] = ((const float4*)g_rw01)[src];
                s23[i] = ((const float4*)g_rw23)[src];
            }
            __syncthreads();

            #pragma unroll
            for (int ky = 0; ky < 3; ky++) {
                const int iy = iy0 + ky;
                if ((unsigned)iy >= HH) continue;
                const float* __restrict__ hrow = hbase + ((size_t)iy*WW)*(COUT*2);
                #pragma unroll
                for (int qq = 0; qq < CHUNK/2; qq++) {
                    const int fq = (cc >> 1) + qq;
                    ulonglong2 hv[10];
                    hv[0] = okL ? *(const ulonglong2*)(hrow + (size_t)(px0-1)*(COUT*2) + fq*4)
                                : make_ulonglong2(0ULL, 0ULL);
                    #pragma unroll
                    for (int j = 1; j < 9; j++)
                        hv[j] = *(const ulonglong2*)(hrow + (size_t)(px0-1+j)*(COUT*2) + fq*4);
                    hv[9] = okR ? *(const ulonglong2*)(hrow + (size_t)(px0+8)*(COUT*2) + fq*4)
                                : make_ulonglong2(0ULL, 0ULL);
                    #pragma unroll
                    for (int kx = 0; kx < 3; kx++) {
                        const int s0 = ((ky*3+kx)*CHUNK + 2*qq)*32 + lane;
                        const ulonglong2 wA0 = *reinterpret_cast<const ulonglong2*>(&s01[s0]);
                        const ulonglong2 wB0 = *reinterpret_cast<const ulonglong2*>(&s23[s0]);
                        const ulonglong2 wA1 = *reinterpret_cast<const ulonglong2*>(&s01[s0+32]);
                        const ulonglong2 wB1 = *reinterpret_cast<const ulonglong2*>(&s23[s0+32]);
                        #pragma unroll
                        for (int p = 0; p < 8; p++) {
                            const u64 se = hv[p + kx].x;
                            const u64 so = hv[p + kx].y;
                            fma_x2(acc[0][p], se, wA0.x);
                            fma_x2(acc[1][p], se, wA0.y);
                            fma_x2(acc[2][p], se, wB0.x);
                            fma_x2(acc[3][p], se, wB0.y);
                            fma_x2(acc[0][p], so, wA1.x);
                            fma_x2(acc[1][p], so, wA1.y);
                            fma_x2(acc[2][p], so, wB1.x);
                            fma_x2(acc[3][p], so, wB1.y);
                        }
                    }
                }
            }
        }
    }

    // BN constants for this thread's 2 channels
    float2 gm  = *(const float2*)(gamma + co0);
    float2 bt2 = *(const float2*)(beta  + co0);
    float2 mm  = *(const float2*)(mmean + co0);
    float2 mv  = *(const float2*)(mvar  + co0);
    float2 inv, add;
    inv.x = gm.x * rsqrtf(mv.x + 1e-3f); add.x = bt2.x - mm.x*inv.x;
    inv.y = gm.y * rsqrtf(mv.y + 1e-3f); add.y = bt2.y - mm.y*inv.y;

    const size_t pixrow = ((size_t)b*HH + py)*WW;
    #pragma unroll
    for (int p = 0; p < 8; p++) {
        const size_t pix = pixrow + px0 + p;

        float2 gi = unpack2(acc[0][p]);
        float2 gf = unpack2(acc[1][p]);
        float2 gg = unpack2(acc[2][p]);
        float2 go = unpack2(acc[3][p]);

        float2 i2, f2, o2;
        i2.x = hsig(gi.x); i2.y = hsig(gi.y);
        f2.x = hsig(gf.x); f2.y = hsig(gf.y);
        o2.x = hsig(go.x); o2.y = hsig(go.y);

        float* __restrict__ cp = g_c + pix*COUT + co0;
        float2 cold = FIRST ? make_float2(0.f,0.f) : *(const float2*)cp;

        float2 cn;
        cn.x = f2.x*cold.x + i2.x*tanhf(gg.x);
        cn.y = f2.y*cold.y + i2.y*tanhf(gg.y);
        *(float2*)cp = cn;

        float2 h2;
        h2.x = o2.x * tanhf(cn.x);
        h2.y = o2.y * tanhf(cn.y);
        *(float4*)(hnewd + pix*(COUT*2) + co0*2) = make_float4(h2.x, h2.x, h2.y, h2.y);

        float2 yv;
        yv.x = h2.x*inv.x + add.x;
        yv.y = h2.y*inv.y + add.y;
        float* __restrict__ yp = y + (gxrow + px0 + p)*COUT + co0;
        *(float2*)yp = yv;
    }
}

extern "C" void kernel_launch(void* const* d_in, const int* in_sizes, int n_in,
                              void* d_out, int out_size)
{
    const float* x      = (const float*)d_in[0];
    const float* wk     = (const float*)d_in[1];
    const float* rw     = (const float*)d_in[2];
    const float* bias   = (const float*)d_in[3];
    const float* gamma  = (const float*)d_in[4];
    const float* beta   = (const float*)d_in[5];
    const float* mmean  = (const float*)d_in[6];
    const float* mvar   = (const float*)d_in[7];
    float* y = (float*)d_out;

    // Prep: transpose/split weights + duplicate x (one-time per launch).
    const int n_prep = 9*COUT*32 + 9*CIN*32;
    prep_weights<<<(n_prep + 127)/128, 128>>>(wk, rw);
    prep_xdup<<<(BB*TT*HH*WW*16)/256, 256>>>(x);

    // Phase 1: all input convs. 8192 blocks x 128 threads (32 px each).
    input_conv_kernel<<<BB*TT*HH*2, 128>>>(bias);

    // Phase 2: 16 sequential recurrent steps. 512 blocks x 128 threads.
    const int nblk = BB*HH*2;
    step_kernel<true><<<nblk, 128>>>(y, 0, gamma, beta, mmean, mvar);
    for (int t = 1; t < TT; t++) {
        step_kernel<false><<<nblk, 128>>>(y, t, gamma, beta, mmean, mvar);
    }
}